// round 3
// baseline (speedup 1.0000x reference)
#include <cuda_runtime.h>

#define NN 50000
#define F_IN 512
#define H1D 64
#define H2D 128
#define NC 10
#define NG 64

// ---- scratch (static device globals; no allocation) ----
__device__ float d_Y[NN * 128];      // [N,128]: cols 0..63 = x@w1_l, 64..127 = x@w1_r
__device__ float d_agg[NN * H1D];    // scatter accumulator (reused for both layers)
__device__ float d_h1[NN * H1D];
__device__ float d_deg[NN];
__device__ float d_gs1[NG * H1D];    // per-graph sum of mean2
__device__ float d_gs2[NG * H1D];    // per-graph sum of h1
__device__ float d_gcnt[NG];

__device__ __forceinline__ int clampi(int v, int lo, int hi) {
    return min(max(v, lo), hi);
}

// ---------------------------------------------------------------- init
__global__ void init_kernel() {
    int i = blockIdx.x * blockDim.x + threadIdx.x;
    if (i < NN * H1D) d_agg[i] = 0.f;
    if (i < NN)       d_deg[i] = 0.f;
    if (i < NG * H1D) { d_gs1[i] = 0.f; d_gs2[i] = 0.f; }
    if (i < NG)       d_gcnt[i] = 0.f;
}

// ---------------------------------------------------------------- degree
__global__ void deg_kernel(const int* __restrict__ ei, int E) {
    int e = blockIdx.x * blockDim.x + threadIdx.x;
    if (e < E) {
        int dst = clampi(ei[E + e], 0, NN - 1);
        atomicAdd(&d_deg[dst], 1.0f);
    }
}

// ---------------------------------------------------------------- SGEMM: Y = x @ [w1_l | w1_r]
// BM=128, BN=128 (full width), BK=16; 256 threads, 8x8 per thread.
__global__ void sgemm_kernel(const float* __restrict__ x,
                             const float* __restrict__ w1l,
                             const float* __restrict__ w1r) {
    __shared__ float As[16][129];   // transposed A tile, +1 pad
    __shared__ float Bs[16][128];

    const int block_row = blockIdx.x * 128;
    const int tid = threadIdx.x;          // 0..255
    const int tx = tid & 15;              // col group
    const int ty = tid >> 4;              // row group

    float acc[8][8];
#pragma unroll
    for (int i = 0; i < 8; i++)
#pragma unroll
        for (int j = 0; j < 8; j++) acc[i][j] = 0.f;

    for (int k0 = 0; k0 < F_IN; k0 += 16) {
        // load A tile: 128 rows x 16 cols, 2 float4 per thread
#pragma unroll
        for (int it = 0; it < 2; it++) {
            int idx = tid + it * 256;     // 0..511
            int r   = idx >> 2;           // 0..127
            int c4  = (idx & 3) << 2;     // 0,4,8,12
            int gr  = block_row + r;
            float4 v = make_float4(0.f, 0.f, 0.f, 0.f);
            if (gr < NN)
                v = *(const float4*)(x + (size_t)gr * F_IN + k0 + c4);
            As[c4 + 0][r] = v.x;
            As[c4 + 1][r] = v.y;
            As[c4 + 2][r] = v.z;
            As[c4 + 3][r] = v.w;
        }
        // load B tile: 16 rows x 128 cols (cols 0..63 from w1l, 64..127 from w1r)
#pragma unroll
        for (int it = 0; it < 2; it++) {
            int idx = tid + it * 256;     // 0..511
            int kk  = idx >> 5;           // 0..15
            int n4  = (idx & 31) << 2;    // 0..124
            const float* wsrc = (n4 < 64)
                ? (w1l + (size_t)(k0 + kk) * H1D + n4)
                : (w1r + (size_t)(k0 + kk) * H1D + (n4 - 64));
            *(float4*)&Bs[kk][n4] = *(const float4*)wsrc;
        }
        __syncthreads();

#pragma unroll
        for (int kk = 0; kk < 16; kk++) {
            float a[8], b[8];
#pragma unroll
            for (int i = 0; i < 8; i++) a[i] = As[kk][ty * 8 + i];
#pragma unroll
            for (int j = 0; j < 8; j++) b[j] = Bs[kk][tx * 8 + j];
#pragma unroll
            for (int i = 0; i < 8; i++)
#pragma unroll
                for (int j = 0; j < 8; j++) acc[i][j] += a[i] * b[j];
        }
        __syncthreads();
    }

#pragma unroll
    for (int i = 0; i < 8; i++) {
        int gr = block_row + ty * 8 + i;
        if (gr < NN) {
            float* dst = d_Y + (size_t)gr * 128 + tx * 8;
            *(float4*)(dst + 0) = make_float4(acc[i][0], acc[i][1], acc[i][2], acc[i][3]);
            *(float4*)(dst + 4) = make_float4(acc[i][4], acc[i][5], acc[i][6], acc[i][7]);
        }
    }
}

// ---------------------------------------------------------------- edge scatter (mean-agg numerator)
// one thread per (edge, 4-feature quad); 16 quads cover 64 features
__global__ void scatter_kernel(const int* __restrict__ ei, int E, int use_h1) {
    int idx = blockIdx.x * blockDim.x + threadIdx.x;
    int e = idx >> 4;
    if (e >= E) return;
    int q = (idx & 15) << 2;
    int s = clampi(ei[e], 0, NN - 1);
    int d = clampi(ei[E + e], 0, NN - 1);
    const float* srcp = use_h1 ? (d_h1 + (size_t)s * H1D + q)
                               : (d_Y  + (size_t)s * 128 + q);   // y_l = cols 0..63
    float4 v = *(const float4*)srcp;
    float* dst = d_agg + (size_t)d * H1D + q;
    atomicAdd(dst + 0, v.x);
    atomicAdd(dst + 1, v.y);
    atomicAdd(dst + 2, v.z);
    atomicAdd(dst + 3, v.w);
}

// ---------------------------------------------------------------- layer-1 epilogue: h1 = relu(agg/deg + y_r + b1), re-zero agg
__global__ void epi1_kernel(const float* __restrict__ b1) {
    int idx = blockIdx.x * blockDim.x + threadIdx.x;
    if (idx >= NN * H1D) return;
    int n = idx >> 6;
    int f = idx & 63;
    float dg = fmaxf(d_deg[n], 1.0f);
    float v = d_agg[idx] / dg + d_Y[(size_t)n * 128 + 64 + f] + b1[f];
    d_h1[idx] = fmaxf(v, 0.f);
    d_agg[idx] = 0.f;
}

// ---------------------------------------------------------------- per-graph reduction (batch is sorted int32)
#define NPB 512
__global__ void reduce_kernel(const int* __restrict__ batch) {
    int f = threadIdx.x & 63;
    int lane = threadIdx.x >> 6;              // 0..3
    int start = blockIdx.x * NPB;
    int end = start + NPB;
    if (end > NN) end = NN;

    float s1 = 0.f, s2 = 0.f, c = 0.f;
    int cur = -1;
    for (int n = start + lane; n < end; n += 4) {
        int g = clampi(batch[n], 0, NG - 1);
        if (g != cur) {
            if (cur >= 0) {
                atomicAdd(&d_gs1[cur * H1D + f], s1);
                atomicAdd(&d_gs2[cur * H1D + f], s2);
                if (f == 0) atomicAdd(&d_gcnt[cur], c);
            }
            cur = g; s1 = 0.f; s2 = 0.f; c = 0.f;
        }
        float dg = fmaxf(d_deg[n], 1.0f);
        s1 += d_agg[(size_t)n * H1D + f] / dg;
        s2 += d_h1[(size_t)n * H1D + f];
        c += 1.0f;
    }
    if (cur >= 0) {
        atomicAdd(&d_gs1[cur * H1D + f], s1);
        atomicAdd(&d_gs2[cur * H1D + f], s2);
        if (f == 0) atomicAdd(&d_gcnt[cur], c);
    }
}

// ---------------------------------------------------------------- final: layer2 GEMM on pooled sums + fc + log_softmax
__global__ void final_kernel(const float* __restrict__ w2l,
                             const float* __restrict__ b2,
                             const float* __restrict__ w2r,
                             const float* __restrict__ wfc,
                             const float* __restrict__ bfc,
                             float* __restrict__ out) {
    __shared__ float pooled[NG][H2D];     // 32KB
    __shared__ float logits[NG][NC];
    int tid = threadIdx.x;                // 256

    for (int idx = tid; idx < NG * H2D; idx += 256) {
        int g = idx >> 7;
        int j = idx & 127;
        float s = 0.f;
        const float* gs1 = d_gs1 + g * H1D;
        const float* gs2 = d_gs2 + g * H1D;
#pragma unroll 8
        for (int f = 0; f < H1D; f++)
            s += gs1[f] * w2l[f * H2D + j] + gs2[f] * w2r[f * H2D + j];
        pooled[g][j] = s / fmaxf(d_gcnt[g], 1.0f) + b2[j];
    }
    __syncthreads();

    for (int idx = tid; idx < NG * NC; idx += 256) {
        int g = idx / NC;
        int c = idx % NC;
        float s = bfc[c];
#pragma unroll 8
        for (int j = 0; j < H2D; j++)
            s += pooled[g][j] * wfc[j * NC + c];
        logits[g][c] = s;
    }
    __syncthreads();

    for (int g = tid; g < NG; g += 256) {
        float mx = -1e30f;
        for (int c = 0; c < NC; c++) mx = fmaxf(mx, logits[g][c]);
        float se = 0.f;
        for (int c = 0; c < NC; c++) se += expf(logits[g][c] - mx);
        float lse = mx + logf(se);
        for (int c = 0; c < NC; c++) out[g * NC + c] = logits[g][c] - lse;
    }
}

// ---------------------------------------------------------------- launch
extern "C" void kernel_launch(void* const* d_in, const int* in_sizes, int n_in,
                              void* d_out, int out_size) {
    const float* x     = (const float*)d_in[0];
    const int*   ei    = (const int*)d_in[1];     // int32 on device (harness dtype set)
    const int*   batch = (const int*)d_in[2];
    const float* w1l   = (const float*)d_in[3];
    const float* b1l   = (const float*)d_in[4];
    const float* w1r   = (const float*)d_in[5];
    const float* w2l   = (const float*)d_in[6];
    const float* b2l   = (const float*)d_in[7];
    const float* w2r   = (const float*)d_in[8];
    const float* wfc   = (const float*)d_in[9];
    const float* bfc   = (const float*)d_in[10];
    float*       out   = (float*)d_out;

    const int E = in_sizes[1] / 2;

    init_kernel<<<(NN * H1D + 255) / 256, 256>>>();
    deg_kernel<<<(E + 255) / 256, 256>>>(ei, E);
    sgemm_kernel<<<(NN + 127) / 128, 256>>>(x, w1l, w1r);
    {
        long long threads = (long long)E * 16;
        scatter_kernel<<<(int)((threads + 255) / 256), 256>>>(ei, E, 0);
    }
    epi1_kernel<<<(NN * H1D + 255) / 256, 256>>>(b1l);
    {
        long long threads = (long long)E * 16;
        scatter_kernel<<<(int)((threads + 255) / 256), 256>>>(ei, E, 1);
    }
    reduce_kernel<<<(NN + NPB - 1) / NPB, 256>>>(batch);
    final_kernel<<<1, 256>>>(w2l, b2l, w2r, wfc, bfc, out);
}

// round 4
// speedup vs baseline: 1.3299x; 1.3299x over previous
#include <cuda_runtime.h>

#define NN 50000
#define F_IN 512
#define H1D 64
#define H2D 128
#define NC 10
#define NG 64

// ---- scratch (static device globals; no allocation) ----
__device__ float d_Y[NN * 128];      // [N,128]: cols 0..63 = x@w1_l, 64..127 = x@w1_r
__device__ float d_agg[NN * H1D];    // scatter accumulator (reused for both layers)
__device__ float d_h1[NN * H1D];
__device__ float d_deg[NN];
__device__ float d_gs1[NG * H1D];    // per-graph sum of mean2
__device__ float d_gs2[NG * H1D];    // per-graph sum of h1
__device__ float d_gcnt[NG];

__device__ __forceinline__ int clampi(int v, int lo, int hi) {
    return min(max(v, lo), hi);
}

__device__ __forceinline__ void red_add_v4(float* p, float4 v) {
    asm volatile("red.global.add.v4.f32 [%0], {%1,%2,%3,%4};"
                 :: "l"(p), "f"(v.x), "f"(v.y), "f"(v.z), "f"(v.w) : "memory");
}

// ---------------------------------------------------------------- init
__global__ void init_kernel() {
    int i = blockIdx.x * blockDim.x + threadIdx.x;
    if (i < NN * H1D) d_agg[i] = 0.f;
    if (i < NN)       d_deg[i] = 0.f;
    if (i < NG * H1D) { d_gs1[i] = 0.f; d_gs2[i] = 0.f; }
    if (i < NG)       d_gcnt[i] = 0.f;
}

// ---------------------------------------------------------------- SGEMM: Y = x @ [w1_l | w1_r]
// BM=128, BN=128, BK=16; 256 threads; 8x8 per thread (chunked 4+4 mapping);
// double-buffered smem, one __syncthreads per K-iter.
__global__ void __launch_bounds__(256) sgemm_kernel(
        const float* __restrict__ x,
        const float* __restrict__ w1l,
        const float* __restrict__ w1r) {
    __shared__ float As[2][16][132];   // transposed A tile, padded
    __shared__ float Bs[2][16][128];

    const int block_row = blockIdx.x * 128;
    const int tid = threadIdx.x;          // 0..255
    const int tx = tid & 15;
    const int ty = tid >> 4;

    float acc[8][8];
#pragma unroll
    for (int i = 0; i < 8; i++)
#pragma unroll
        for (int j = 0; j < 8; j++) acc[i][j] = 0.f;

    // per-thread load coords (constant across iters)
    const int a_r0  = (tid * 2) >> 2 >> 1;               // unused placeholder avoidance
    (void)a_r0;
    // A tile: idx = tid + it*256 (it=0,1): r = idx>>2 (0..127), c4 = (idx&3)*4
    // B tile: idx = tid + it*256: kk = idx>>5 (0..15), n4 = (idx&31)*4

    float4 pa[2], pb[2];

    // ---- load first tile (k0 = 0) into buffer 0 ----
#pragma unroll
    for (int it = 0; it < 2; it++) {
        int idx = tid + it * 256;
        int r   = idx >> 2;
        int c4  = (idx & 3) << 2;
        int gr  = block_row + r;
        float4 v = make_float4(0.f, 0.f, 0.f, 0.f);
        if (gr < NN) v = *(const float4*)(x + (size_t)gr * F_IN + c4);
        As[0][c4 + 0][r] = v.x;
        As[0][c4 + 1][r] = v.y;
        As[0][c4 + 2][r] = v.z;
        As[0][c4 + 3][r] = v.w;
    }
#pragma unroll
    for (int it = 0; it < 2; it++) {
        int idx = tid + it * 256;
        int kk  = idx >> 5;
        int n4  = (idx & 31) << 2;
        const float* wsrc = (n4 < 64)
            ? (w1l + (size_t)kk * H1D + n4)
            : (w1r + (size_t)kk * H1D + (n4 - 64));
        *(float4*)&Bs[0][kk][n4] = *(const float4*)wsrc;
    }
    __syncthreads();

    int cur = 0;
    for (int k0 = 0; k0 < F_IN; k0 += 16) {
        const int knext = k0 + 16;
        const bool has_next = (knext < F_IN);

        // prefetch next tile into registers
        if (has_next) {
#pragma unroll
            for (int it = 0; it < 2; it++) {
                int idx = tid + it * 256;
                int r   = idx >> 2;
                int c4  = (idx & 3) << 2;
                int gr  = block_row + r;
                pa[it] = make_float4(0.f, 0.f, 0.f, 0.f);
                if (gr < NN)
                    pa[it] = *(const float4*)(x + (size_t)gr * F_IN + knext + c4);
            }
#pragma unroll
            for (int it = 0; it < 2; it++) {
                int idx = tid + it * 256;
                int kk  = idx >> 5;
                int n4  = (idx & 31) << 2;
                const float* wsrc = (n4 < 64)
                    ? (w1l + (size_t)(knext + kk) * H1D + n4)
                    : (w1r + (size_t)(knext + kk) * H1D + (n4 - 64));
                pb[it] = *(const float4*)wsrc;
            }
        }

        // compute on buffer `cur`
#pragma unroll
        for (int kk = 0; kk < 16; kk++) {
            float4 a0 = *(const float4*)&As[cur][kk][ty * 4];
            float4 a1 = *(const float4*)&As[cur][kk][64 + ty * 4];
            float4 b0 = *(const float4*)&Bs[cur][kk][tx * 4];
            float4 b1 = *(const float4*)&Bs[cur][kk][64 + tx * 4];
            float a[8] = {a0.x, a0.y, a0.z, a0.w, a1.x, a1.y, a1.z, a1.w};
            float b[8] = {b0.x, b0.y, b0.z, b0.w, b1.x, b1.y, b1.z, b1.w};
#pragma unroll
            for (int i = 0; i < 8; i++)
#pragma unroll
                for (int j = 0; j < 8; j++) acc[i][j] += a[i] * b[j];
        }

        // store prefetched regs into the other buffer
        if (has_next) {
            int nxt = cur ^ 1;
#pragma unroll
            for (int it = 0; it < 2; it++) {
                int idx = tid + it * 256;
                int r   = idx >> 2;
                int c4  = (idx & 3) << 2;
                As[nxt][c4 + 0][r] = pa[it].x;
                As[nxt][c4 + 1][r] = pa[it].y;
                As[nxt][c4 + 2][r] = pa[it].z;
                As[nxt][c4 + 3][r] = pa[it].w;
            }
#pragma unroll
            for (int it = 0; it < 2; it++) {
                int idx = tid + it * 256;
                int kk  = idx >> 5;
                int n4  = (idx & 31) << 2;
                *(float4*)&Bs[nxt][kk][n4] = pb[it];
            }
            __syncthreads();
            cur = nxt;
        }
    }

    // epilogue: rows ty*4+{0..3} and 64+ty*4+{0..3}; col chunks tx*4, 64+tx*4
#pragma unroll
    for (int i = 0; i < 8; i++) {
        int r  = (i < 4) ? (ty * 4 + i) : (64 + ty * 4 + i - 4);
        int gr = block_row + r;
        if (gr < NN) {
            float* dst = d_Y + (size_t)gr * 128;
            *(float4*)(dst + tx * 4)      = make_float4(acc[i][0], acc[i][1], acc[i][2], acc[i][3]);
            *(float4*)(dst + 64 + tx * 4) = make_float4(acc[i][4], acc[i][5], acc[i][6], acc[i][7]);
        }
    }
}

// ---------------------------------------------------------------- edge scatter (mean-agg numerator)
// one thread per (edge, 4-feature quad); 16 quads cover 64 features.
// pass 0 also accumulates degree (from quad 0).
__global__ void scatter_kernel(const int* __restrict__ ei, int E, int use_h1) {
    int idx = blockIdx.x * blockDim.x + threadIdx.x;
    int e = idx >> 4;
    if (e >= E) return;
    int q = (idx & 15) << 2;
    int s = clampi(ei[e], 0, NN - 1);
    int d = clampi(ei[E + e], 0, NN - 1);
    const float* srcp = use_h1 ? (d_h1 + (size_t)s * H1D + q)
                               : (d_Y  + (size_t)s * 128 + q);   // y_l = cols 0..63
    float4 v = *(const float4*)srcp;
    red_add_v4(d_agg + (size_t)d * H1D + q, v);
    if (!use_h1 && q == 0) atomicAdd(&d_deg[d], 1.0f);
}

// ---------------------------------------------------------------- layer-1 epilogue: h1 = relu(agg/deg + y_r + b1), re-zero agg
__global__ void epi1_kernel(const float* __restrict__ b1) {
    int idx = blockIdx.x * blockDim.x + threadIdx.x;
    if (idx >= NN * H1D) return;
    int n = idx >> 6;
    int f = idx & 63;
    float dg = fmaxf(d_deg[n], 1.0f);
    float v = d_agg[idx] / dg + d_Y[(size_t)n * 128 + 64 + f] + b1[f];
    d_h1[idx] = fmaxf(v, 0.f);
    d_agg[idx] = 0.f;
}

// ---------------------------------------------------------------- per-graph reduction (batch is sorted int32)
#define NPB 512
__global__ void reduce_kernel(const int* __restrict__ batch) {
    int f = threadIdx.x & 63;
    int lane = threadIdx.x >> 6;              // 0..3
    int start = blockIdx.x * NPB;
    int end = start + NPB;
    if (end > NN) end = NN;

    float s1 = 0.f, s2 = 0.f, c = 0.f;
    int cur = -1;
    for (int n = start + lane; n < end; n += 4) {
        int g = clampi(batch[n], 0, NG - 1);
        if (g != cur) {
            if (cur >= 0) {
                atomicAdd(&d_gs1[cur * H1D + f], s1);
                atomicAdd(&d_gs2[cur * H1D + f], s2);
                if (f == 0) atomicAdd(&d_gcnt[cur], c);
            }
            cur = g; s1 = 0.f; s2 = 0.f; c = 0.f;
        }
        float dg = fmaxf(d_deg[n], 1.0f);
        s1 += d_agg[(size_t)n * H1D + f] / dg;
        s2 += d_h1[(size_t)n * H1D + f];
        c += 1.0f;
    }
    if (cur >= 0) {
        atomicAdd(&d_gs1[cur * H1D + f], s1);
        atomicAdd(&d_gs2[cur * H1D + f], s2);
        if (f == 0) atomicAdd(&d_gcnt[cur], c);
    }
}

// ---------------------------------------------------------------- final: layer2 GEMM on pooled sums + fc + log_softmax
__global__ void final_kernel(const float* __restrict__ w2l,
                             const float* __restrict__ b2,
                             const float* __restrict__ w2r,
                             const float* __restrict__ wfc,
                             const float* __restrict__ bfc,
                             float* __restrict__ out) {
    __shared__ float pooled[NG][H2D];     // 32KB
    __shared__ float logits[NG][NC];
    int tid = threadIdx.x;                // 256

    for (int idx = tid; idx < NG * H2D; idx += 256) {
        int g = idx >> 7;
        int j = idx & 127;
        float s = 0.f;
        const float* gs1 = d_gs1 + g * H1D;
        const float* gs2 = d_gs2 + g * H1D;
#pragma unroll 8
        for (int f = 0; f < H1D; f++)
            s += gs1[f] * w2l[f * H2D + j] + gs2[f] * w2r[f * H2D + j];
        pooled[g][j] = s / fmaxf(d_gcnt[g], 1.0f) + b2[j];
    }
    __syncthreads();

    for (int idx = tid; idx < NG * NC; idx += 256) {
        int g = idx / NC;
        int c = idx % NC;
        float s = bfc[c];
#pragma unroll 8
        for (int j = 0; j < H2D; j++)
            s += pooled[g][j] * wfc[j * NC + c];
        logits[g][c] = s;
    }
    __syncthreads();

    for (int g = tid; g < NG; g += 256) {
        float mx = -1e30f;
        for (int c = 0; c < NC; c++) mx = fmaxf(mx, logits[g][c]);
        float se = 0.f;
        for (int c = 0; c < NC; c++) se += expf(logits[g][c] - mx);
        float lse = mx + logf(se);
        for (int c = 0; c < NC; c++) out[g * NC + c] = logits[g][c] - lse;
    }
}

// ---------------------------------------------------------------- launch
extern "C" void kernel_launch(void* const* d_in, const int* in_sizes, int n_in,
                              void* d_out, int out_size) {
    const float* x     = (const float*)d_in[0];
    const int*   ei    = (const int*)d_in[1];
    const int*   batch = (const int*)d_in[2];
    const float* w1l   = (const float*)d_in[3];
    const float* b1l   = (const float*)d_in[4];
    const float* w1r   = (const float*)d_in[5];
    const float* w2l   = (const float*)d_in[6];
    const float* b2l   = (const float*)d_in[7];
    const float* w2r   = (const float*)d_in[8];
    const float* wfc   = (const float*)d_in[9];
    const float* bfc   = (const float*)d_in[10];
    float*       out   = (float*)d_out;

    const int E = in_sizes[1] / 2;

    init_kernel<<<(NN * H1D + 255) / 256, 256>>>();
    sgemm_kernel<<<(NN + 127) / 128, 256>>>(x, w1l, w1r);
    {
        long long threads = (long long)E * 16;
        scatter_kernel<<<(int)((threads + 255) / 256), 256>>>(ei, E, 0);
    }
    epi1_kernel<<<(NN * H1D + 255) / 256, 256>>>(b1l);
    {
        long long threads = (long long)E * 16;
        scatter_kernel<<<(int)((threads + 255) / 256), 256>>>(ei, E, 1);
    }
    reduce_kernel<<<(NN + NPB - 1) / NPB, 256>>>(batch);
    final_kernel<<<1, 256>>>(w2l, b2l, w2r, wfc, bfc, out);
}

// round 5
// speedup vs baseline: 1.5616x; 1.1742x over previous
#include <cuda_runtime.h>
#include <cstdint>

#define NN 50000
#define F_IN 512
#define H1D 64
#define H2D 128
#define NC 10
#define NG 64

// ---- scratch (static device globals; no allocation) ----
__device__ float d_Y[NN * 128];      // [N,128]: cols 0..63 = x@w1_l, 64..127 = x@w1_r
__device__ float d_agg[NN * H1D];    // scatter accumulator (reused for both layers)
__device__ float d_h1[NN * H1D];
__device__ float d_deg[NN];
__device__ float d_gs1[NG * H1D];
__device__ float d_gs2[NG * H1D];
__device__ float d_gcnt[NG];

__device__ __forceinline__ int clampi(int v, int lo, int hi) {
    return min(max(v, lo), hi);
}

__device__ __forceinline__ void red_add_v4(float* p, float4 v) {
    asm volatile("red.global.add.v4.f32 [%0], {%1,%2,%3,%4};"
                 :: "l"(p), "f"(v.x), "f"(v.y), "f"(v.z), "f"(v.w) : "memory");
}

__device__ __forceinline__ float cvt_tf32(float f) {
    uint32_t u;
    asm("cvt.rna.tf32.f32 %0, %1;" : "=r"(u) : "f"(f));
    return __uint_as_float(u);
}

__device__ __forceinline__ void mma_tf32(float& d0, float& d1, float& d2, float& d3,
                                         uint32_t a0, uint32_t a1, uint32_t a2, uint32_t a3,
                                         uint32_t b0, uint32_t b1) {
    asm volatile("mma.sync.aligned.m16n8k8.row.col.f32.tf32.tf32.f32 "
                 "{%0,%1,%2,%3}, {%4,%5,%6,%7}, {%8,%9}, {%0,%1,%2,%3};"
                 : "+f"(d0), "+f"(d1), "+f"(d2), "+f"(d3)
                 : "r"(a0), "r"(a1), "r"(a2), "r"(a3), "r"(b0), "r"(b1));
}

// ---------------------------------------------------------------- init
__global__ void init_kernel() {
    int i = blockIdx.x * blockDim.x + threadIdx.x;
    if (i < NN * H1D) d_agg[i] = 0.f;
    if (i < NN)       d_deg[i] = 0.f;
    if (i < NG * H1D) { d_gs1[i] = 0.f; d_gs2[i] = 0.f; }
    if (i < NG)       d_gcnt[i] = 0.f;
}

// ---------------------------------------------------------------- tf32 tensor-core GEMM: Y = x @ [w1_l | w1_r]
// BM=128, BN=128, BK=16; 256 threads, 8 warps (2 M x 4 N), warp tile 64x32.
// As stride 20 and Bs stride 136 are conflict-free for the fragment patterns.
#define AS_STRIDE 20
#define BS_STRIDE 136
__global__ void __launch_bounds__(256) tf32gemm_kernel(
        const float* __restrict__ x,
        const float* __restrict__ w1l,
        const float* __restrict__ w1r) {
    __shared__ float As[2][128][AS_STRIDE];
    __shared__ float Bs[2][16][BS_STRIDE];

    const int block_row = blockIdx.x * 128;
    const int tid  = threadIdx.x;
    const int lane = tid & 31;
    const int wid  = tid >> 5;
    const int warp_m = wid >> 2;          // 0..1 -> 64-row half
    const int warp_n = wid & 3;           // 0..3 -> 32-col quarter
    const int gId  = lane >> 2;           // 0..7
    const int t4   = lane & 3;            // 0..3

    float acc[4][4][4];
#pragma unroll
    for (int mf = 0; mf < 4; mf++)
#pragma unroll
        for (int nf = 0; nf < 4; nf++)
#pragma unroll
            for (int r = 0; r < 4; r++) acc[mf][nf][r] = 0.f;

    // staging coords (constant): A: idx=tid+it*256 -> row=idx>>2, c4=(idx&3)*4
    //                            B: idx=tid+it*256 -> kk=idx>>5, n4=(idx&31)*4
    float4 pa[2], pb[2];

    // prologue: tile 0 into buffer 0
#pragma unroll
    for (int it = 0; it < 2; it++) {
        int idx = tid + it * 256;
        int r   = idx >> 2;
        int c4  = (idx & 3) << 2;
        int gr  = block_row + r;
        float4 v = make_float4(0.f, 0.f, 0.f, 0.f);
        if (gr < NN) v = *(const float4*)(x + (size_t)gr * F_IN + c4);
        As[0][r][c4 + 0] = cvt_tf32(v.x);
        As[0][r][c4 + 1] = cvt_tf32(v.y);
        As[0][r][c4 + 2] = cvt_tf32(v.z);
        As[0][r][c4 + 3] = cvt_tf32(v.w);
    }
#pragma unroll
    for (int it = 0; it < 2; it++) {
        int idx = tid + it * 256;
        int kk  = idx >> 5;
        int n4  = (idx & 31) << 2;
        const float* wsrc = (n4 < 64)
            ? (w1l + (size_t)kk * H1D + n4)
            : (w1r + (size_t)kk * H1D + (n4 - 64));
        float4 v = *(const float4*)wsrc;
        Bs[0][kk][n4 + 0] = cvt_tf32(v.x);
        Bs[0][kk][n4 + 1] = cvt_tf32(v.y);
        Bs[0][kk][n4 + 2] = cvt_tf32(v.z);
        Bs[0][kk][n4 + 3] = cvt_tf32(v.w);
    }
    __syncthreads();

    int cur = 0;
    for (int kt = 0; kt < F_IN / 16; kt++) {
        const int knext = (kt + 1) * 16;
        const bool has_next = (knext < F_IN);

        if (has_next) {
#pragma unroll
            for (int it = 0; it < 2; it++) {
                int idx = tid + it * 256;
                int r   = idx >> 2;
                int c4  = (idx & 3) << 2;
                int gr  = block_row + r;
                pa[it] = make_float4(0.f, 0.f, 0.f, 0.f);
                if (gr < NN)
                    pa[it] = *(const float4*)(x + (size_t)gr * F_IN + knext + c4);
            }
#pragma unroll
            for (int it = 0; it < 2; it++) {
                int idx = tid + it * 256;
                int kk  = idx >> 5;
                int n4  = (idx & 31) << 2;
                const float* wsrc = (n4 < 64)
                    ? (w1l + (size_t)(knext + kk) * H1D + n4)
                    : (w1r + (size_t)(knext + kk) * H1D + (n4 - 64));
                pb[it] = *(const float4*)wsrc;
            }
        }

        // compute on buffer cur: 2 k-steps of 8
#pragma unroll
        for (int k8 = 0; k8 < 2; k8++) {
            const int kc = k8 * 8 + t4;
            uint32_t a[4][4], b[4][2];
#pragma unroll
            for (int mf = 0; mf < 4; mf++) {
                int row = warp_m * 64 + mf * 16 + gId;
                a[mf][0] = __float_as_uint(As[cur][row][kc]);
                a[mf][1] = __float_as_uint(As[cur][row + 8][kc]);
                a[mf][2] = __float_as_uint(As[cur][row][kc + 4]);
                a[mf][3] = __float_as_uint(As[cur][row + 8][kc + 4]);
            }
#pragma unroll
            for (int nf = 0; nf < 4; nf++) {
                int col = warp_n * 32 + nf * 8 + gId;
                b[nf][0] = __float_as_uint(Bs[cur][k8 * 8 + t4][col]);
                b[nf][1] = __float_as_uint(Bs[cur][k8 * 8 + t4 + 4][col]);
            }
#pragma unroll
            for (int mf = 0; mf < 4; mf++)
#pragma unroll
                for (int nf = 0; nf < 4; nf++)
                    mma_tf32(acc[mf][nf][0], acc[mf][nf][1], acc[mf][nf][2], acc[mf][nf][3],
                             a[mf][0], a[mf][1], a[mf][2], a[mf][3],
                             b[nf][0], b[nf][1]);
        }

        if (has_next) {
            int nxt = cur ^ 1;
#pragma unroll
            for (int it = 0; it < 2; it++) {
                int idx = tid + it * 256;
                int r   = idx >> 2;
                int c4  = (idx & 3) << 2;
                As[nxt][r][c4 + 0] = cvt_tf32(pa[it].x);
                As[nxt][r][c4 + 1] = cvt_tf32(pa[it].y);
                As[nxt][r][c4 + 2] = cvt_tf32(pa[it].z);
                As[nxt][r][c4 + 3] = cvt_tf32(pa[it].w);
            }
#pragma unroll
            for (int it = 0; it < 2; it++) {
                int idx = tid + it * 256;
                int kk  = idx >> 5;
                int n4  = (idx & 31) << 2;
                Bs[nxt][kk][n4 + 0] = cvt_tf32(pb[it].x);
                Bs[nxt][kk][n4 + 1] = cvt_tf32(pb[it].y);
                Bs[nxt][kk][n4 + 2] = cvt_tf32(pb[it].z);
                Bs[nxt][kk][n4 + 3] = cvt_tf32(pb[it].w);
            }
            __syncthreads();
            cur = nxt;
        }
    }

    // epilogue: d0,d1 -> (row, col..col+1); d2,d3 -> (row+8, col..col+1)
#pragma unroll
    for (int mf = 0; mf < 4; mf++) {
        int row0 = block_row + warp_m * 64 + mf * 16 + gId;
#pragma unroll
        for (int nf = 0; nf < 4; nf++) {
            int col = warp_n * 32 + nf * 8 + t4 * 2;
            if (row0 < NN)
                *(float2*)(d_Y + (size_t)row0 * 128 + col) =
                    make_float2(acc[mf][nf][0], acc[mf][nf][1]);
            if (row0 + 8 < NN)
                *(float2*)(d_Y + (size_t)(row0 + 8) * 128 + col) =
                    make_float2(acc[mf][nf][2], acc[mf][nf][3]);
        }
    }
}

// ---------------------------------------------------------------- edge scatter (mean-agg numerator)
__global__ void scatter_kernel(const int* __restrict__ ei, int E, int use_h1) {
    int idx = blockIdx.x * blockDim.x + threadIdx.x;
    int e = idx >> 4;
    if (e >= E) return;
    int q = (idx & 15) << 2;
    int s = clampi(ei[e], 0, NN - 1);
    int d = clampi(ei[E + e], 0, NN - 1);
    const float* srcp = use_h1 ? (d_h1 + (size_t)s * H1D + q)
                               : (d_Y  + (size_t)s * 128 + q);   // y_l = cols 0..63
    float4 v = *(const float4*)srcp;
    red_add_v4(d_agg + (size_t)d * H1D + q, v);
    if (!use_h1 && q == 0) atomicAdd(&d_deg[d], 1.0f);
}

// ---------------------------------------------------------------- layer-1 epilogue
__global__ void epi1_kernel(const float* __restrict__ b1) {
    int idx = blockIdx.x * blockDim.x + threadIdx.x;
    if (idx >= NN * H1D) return;
    int n = idx >> 6;
    int f = idx & 63;
    float dg = fmaxf(d_deg[n], 1.0f);
    float v = d_agg[idx] / dg + d_Y[(size_t)n * 128 + 64 + f] + b1[f];
    d_h1[idx] = fmaxf(v, 0.f);
    d_agg[idx] = 0.f;
}

// ---------------------------------------------------------------- per-graph reduction (batch is sorted int32)
#define NPB 512
__global__ void reduce_kernel(const int* __restrict__ batch) {
    int f = threadIdx.x & 63;
    int lane = threadIdx.x >> 6;
    int start = blockIdx.x * NPB;
    int end = start + NPB;
    if (end > NN) end = NN;

    float s1 = 0.f, s2 = 0.f, c = 0.f;
    int cur = -1;
    for (int n = start + lane; n < end; n += 4) {
        int g = clampi(batch[n], 0, NG - 1);
        if (g != cur) {
            if (cur >= 0) {
                atomicAdd(&d_gs1[cur * H1D + f], s1);
                atomicAdd(&d_gs2[cur * H1D + f], s2);
                if (f == 0) atomicAdd(&d_gcnt[cur], c);
            }
            cur = g; s1 = 0.f; s2 = 0.f; c = 0.f;
        }
        float dg = fmaxf(d_deg[n], 1.0f);
        s1 += d_agg[(size_t)n * H1D + f] / dg;
        s2 += d_h1[(size_t)n * H1D + f];
        c += 1.0f;
    }
    if (cur >= 0) {
        atomicAdd(&d_gs1[cur * H1D + f], s1);
        atomicAdd(&d_gs2[cur * H1D + f], s2);
        if (f == 0) atomicAdd(&d_gcnt[cur], c);
    }
}

// ---------------------------------------------------------------- final
__global__ void final_kernel(const float* __restrict__ w2l,
                             const float* __restrict__ b2,
                             const float* __restrict__ w2r,
                             const float* __restrict__ wfc,
                             const float* __restrict__ bfc,
                             float* __restrict__ out) {
    __shared__ float pooled[NG][H2D];
    __shared__ float logits[NG][NC];
    int tid = threadIdx.x;

    for (int idx = tid; idx < NG * H2D; idx += 256) {
        int g = idx >> 7;
        int j = idx & 127;
        float s = 0.f;
        const float* gs1 = d_gs1 + g * H1D;
        const float* gs2 = d_gs2 + g * H1D;
#pragma unroll 8
        for (int f = 0; f < H1D; f++)
            s += gs1[f] * w2l[f * H2D + j] + gs2[f] * w2r[f * H2D + j];
        pooled[g][j] = s / fmaxf(d_gcnt[g], 1.0f) + b2[j];
    }
    __syncthreads();

    for (int idx = tid; idx < NG * NC; idx += 256) {
        int g = idx / NC;
        int c = idx % NC;
        float s = bfc[c];
#pragma unroll 8
        for (int j = 0; j < H2D; j++)
            s += pooled[g][j] * wfc[j * NC + c];
        logits[g][c] = s;
    }
    __syncthreads();

    for (int g = tid; g < NG; g += 256) {
        float mx = -1e30f;
        for (int c = 0; c < NC; c++) mx = fmaxf(mx, logits[g][c]);
        float se = 0.f;
        for (int c = 0; c < NC; c++) se += expf(logits[g][c] - mx);
        float lse = mx + logf(se);
        for (int c = 0; c < NC; c++) out[g * NC + c] = logits[g][c] - lse;
    }
}

// ---------------------------------------------------------------- launch
extern "C" void kernel_launch(void* const* d_in, const int* in_sizes, int n_in,
                              void* d_out, int out_size) {
    const float* x     = (const float*)d_in[0];
    const int*   ei    = (const int*)d_in[1];
    const int*   batch = (const int*)d_in[2];
    const float* w1l   = (const float*)d_in[3];
    const float* b1l   = (const float*)d_in[4];
    const float* w1r   = (const float*)d_in[5];
    const float* w2l   = (const float*)d_in[6];
    const float* b2l   = (const float*)d_in[7];
    const float* w2r   = (const float*)d_in[8];
    const float* wfc   = (const float*)d_in[9];
    const float* bfc   = (const float*)d_in[10];
    float*       out   = (float*)d_out;

    const int E = in_sizes[1] / 2;

    init_kernel<<<(NN * H1D + 255) / 256, 256>>>();
    tf32gemm_kernel<<<(NN + 127) / 128, 256>>>(x, w1l, w1r);
    {
        long long threads = (long long)E * 16;
        scatter_kernel<<<(int)((threads + 255) / 256), 256>>>(ei, E, 0);
    }
    epi1_kernel<<<(NN * H1D + 255) / 256, 256>>>(b1l);
    {
        long long threads = (long long)E * 16;
        scatter_kernel<<<(int)((threads + 255) / 256), 256>>>(ei, E, 1);
    }
    reduce_kernel<<<(NN + NPB - 1) / NPB, 256>>>(batch);
    final_kernel<<<1, 256>>>(w2l, b2l, w2r, wfc, bfc, out);
}

// round 6
// speedup vs baseline: 1.6612x; 1.0638x over previous
#include <cuda_runtime.h>
#include <cstdint>

#define NN 50000
#define EMAX 800000
#define F_IN 512
#define H1D 64
#define H2D 128
#define NC 10
#define NG 64

// ---- scratch (static device globals; no allocation) ----
__device__ float d_Y[NN * 128];      // [N,128]: cols 0..63 = x@w1_l, 64..127 = x@w1_r
__device__ float d_h1[NN * H1D];
__device__ float d_mean2[NN * H1D];  // layer-2 neighbor means
__device__ int   d_degi[NN];
__device__ int   d_off[NN + 1];
__device__ int   d_fill[NN];
__device__ int   d_csr_src[EMAX];
__device__ float d_gs1[NG * H1D];
__device__ float d_gs2[NG * H1D];
__device__ float d_gcnt[NG];

__device__ __forceinline__ int clampi(int v, int lo, int hi) {
    return min(max(v, lo), hi);
}

__device__ __forceinline__ float cvt_tf32(float f) {
    uint32_t u;
    asm("cvt.rna.tf32.f32 %0, %1;" : "=r"(u) : "f"(f));
    return __uint_as_float(u);
}

__device__ __forceinline__ void mma_tf32(float& d0, float& d1, float& d2, float& d3,
                                         uint32_t a0, uint32_t a1, uint32_t a2, uint32_t a3,
                                         uint32_t b0, uint32_t b1) {
    asm volatile("mma.sync.aligned.m16n8k8.row.col.f32.tf32.tf32.f32 "
                 "{%0,%1,%2,%3}, {%4,%5,%6,%7}, {%8,%9}, {%0,%1,%2,%3};"
                 : "+f"(d0), "+f"(d1), "+f"(d2), "+f"(d3)
                 : "r"(a0), "r"(a1), "r"(a2), "r"(a3), "r"(b0), "r"(b1));
}

// ---------------------------------------------------------------- init
__global__ void init_kernel() {
    int i = blockIdx.x * blockDim.x + threadIdx.x;
    if (i < NN) { d_degi[i] = 0; d_fill[i] = 0; }
    if (i < NG * H1D) { d_gs1[i] = 0.f; d_gs2[i] = 0.f; }
    if (i < NG) d_gcnt[i] = 0.f;
}

// ---------------------------------------------------------------- degree histogram
__global__ void deg_kernel(const int* __restrict__ ei, int E) {
    int e = blockIdx.x * blockDim.x + threadIdx.x;
    if (e < E) atomicAdd(&d_degi[clampi(ei[E + e], 0, NN - 1)], 1);
}

// ---------------------------------------------------------------- exclusive scan over d_degi (single block, 1024 threads)
__global__ void scan_kernel() {
    const int T = 1024;
    int tid = threadIdx.x;
    int per = (NN + T - 1) / T;
    int start = tid * per;
    int end = min(start + per, NN);

    int sum = 0;
    for (int i = start; i < end; i++) sum += d_degi[i];

    __shared__ int warp_sums[32];
    int lane = tid & 31, w = tid >> 5;
    int v = sum;
#pragma unroll
    for (int o = 1; o < 32; o <<= 1) {
        int n = __shfl_up_sync(~0u, v, o);
        if (lane >= o) v += n;
    }
    if (lane == 31) warp_sums[w] = v;
    __syncthreads();
    if (w == 0) {
        int s = warp_sums[lane];
#pragma unroll
        for (int o = 1; o < 32; o <<= 1) {
            int n = __shfl_up_sync(~0u, s, o);
            if (lane >= o) s += n;
        }
        warp_sums[lane] = s;
    }
    __syncthreads();

    int excl = v - sum + (w > 0 ? warp_sums[w - 1] : 0);
    int run = excl;
    for (int i = start; i < end; i++) { d_off[i] = run; run += d_degi[i]; }
    if (tid == T - 1) d_off[NN] = run;
}

// ---------------------------------------------------------------- CSR fill
__global__ void fill_kernel(const int* __restrict__ ei, int E) {
    int e = blockIdx.x * blockDim.x + threadIdx.x;
    if (e >= E) return;
    int s = clampi(ei[e], 0, NN - 1);
    int d = clampi(ei[E + e], 0, NN - 1);
    int pos = d_off[d] + atomicAdd(&d_fill[d], 1);
    if (pos < EMAX) d_csr_src[pos] = s;
}

// ---------------------------------------------------------------- tf32 tensor-core GEMM: Y = x @ [w1_l | w1_r]
#define AS_STRIDE 20
#define BS_STRIDE 136
__global__ void __launch_bounds__(256) tf32gemm_kernel(
        const float* __restrict__ x,
        const float* __restrict__ w1l,
        const float* __restrict__ w1r) {
    __shared__ float As[2][128][AS_STRIDE];
    __shared__ float Bs[2][16][BS_STRIDE];

    const int block_row = blockIdx.x * 128;
    const int tid  = threadIdx.x;
    const int lane = tid & 31;
    const int wid  = tid >> 5;
    const int warp_m = wid >> 2;
    const int warp_n = wid & 3;
    const int gId  = lane >> 2;
    const int t4   = lane & 3;

    float acc[4][4][4];
#pragma unroll
    for (int mf = 0; mf < 4; mf++)
#pragma unroll
        for (int nf = 0; nf < 4; nf++)
#pragma unroll
            for (int r = 0; r < 4; r++) acc[mf][nf][r] = 0.f;

    float4 pa[2], pb[2];

#pragma unroll
    for (int it = 0; it < 2; it++) {
        int idx = tid + it * 256;
        int r   = idx >> 2;
        int c4  = (idx & 3) << 2;
        int gr  = block_row + r;
        float4 v = make_float4(0.f, 0.f, 0.f, 0.f);
        if (gr < NN) v = *(const float4*)(x + (size_t)gr * F_IN + c4);
        As[0][r][c4 + 0] = cvt_tf32(v.x);
        As[0][r][c4 + 1] = cvt_tf32(v.y);
        As[0][r][c4 + 2] = cvt_tf32(v.z);
        As[0][r][c4 + 3] = cvt_tf32(v.w);
    }
#pragma unroll
    for (int it = 0; it < 2; it++) {
        int idx = tid + it * 256;
        int kk  = idx >> 5;
        int n4  = (idx & 31) << 2;
        const float* wsrc = (n4 < 64)
            ? (w1l + (size_t)kk * H1D + n4)
            : (w1r + (size_t)kk * H1D + (n4 - 64));
        float4 v = *(const float4*)wsrc;
        Bs[0][kk][n4 + 0] = cvt_tf32(v.x);
        Bs[0][kk][n4 + 1] = cvt_tf32(v.y);
        Bs[0][kk][n4 + 2] = cvt_tf32(v.z);
        Bs[0][kk][n4 + 3] = cvt_tf32(v.w);
    }
    __syncthreads();

    int cur = 0;
    for (int kt = 0; kt < F_IN / 16; kt++) {
        const int knext = (kt + 1) * 16;
        const bool has_next = (knext < F_IN);

        if (has_next) {
#pragma unroll
            for (int it = 0; it < 2; it++) {
                int idx = tid + it * 256;
                int r   = idx >> 2;
                int c4  = (idx & 3) << 2;
                int gr  = block_row + r;
                pa[it] = make_float4(0.f, 0.f, 0.f, 0.f);
                if (gr < NN)
                    pa[it] = *(const float4*)(x + (size_t)gr * F_IN + knext + c4);
            }
#pragma unroll
            for (int it = 0; it < 2; it++) {
                int idx = tid + it * 256;
                int kk  = idx >> 5;
                int n4  = (idx & 31) << 2;
                const float* wsrc = (n4 < 64)
                    ? (w1l + (size_t)(knext + kk) * H1D + n4)
                    : (w1r + (size_t)(knext + kk) * H1D + (n4 - 64));
                pb[it] = *(const float4*)wsrc;
            }
        }

#pragma unroll
        for (int k8 = 0; k8 < 2; k8++) {
            const int kc = k8 * 8 + t4;
            uint32_t a[4][4], b[4][2];
#pragma unroll
            for (int mf = 0; mf < 4; mf++) {
                int row = warp_m * 64 + mf * 16 + gId;
                a[mf][0] = __float_as_uint(As[cur][row][kc]);
                a[mf][1] = __float_as_uint(As[cur][row + 8][kc]);
                a[mf][2] = __float_as_uint(As[cur][row][kc + 4]);
                a[mf][3] = __float_as_uint(As[cur][row + 8][kc + 4]);
            }
#pragma unroll
            for (int nf = 0; nf < 4; nf++) {
                int col = warp_n * 32 + nf * 8 + gId;
                b[nf][0] = __float_as_uint(Bs[cur][k8 * 8 + t4][col]);
                b[nf][1] = __float_as_uint(Bs[cur][k8 * 8 + t4 + 4][col]);
            }
#pragma unroll
            for (int mf = 0; mf < 4; mf++)
#pragma unroll
                for (int nf = 0; nf < 4; nf++)
                    mma_tf32(acc[mf][nf][0], acc[mf][nf][1], acc[mf][nf][2], acc[mf][nf][3],
                             a[mf][0], a[mf][1], a[mf][2], a[mf][3],
                             b[nf][0], b[nf][1]);
        }

        if (has_next) {
            int nxt = cur ^ 1;
#pragma unroll
            for (int it = 0; it < 2; it++) {
                int idx = tid + it * 256;
                int r   = idx >> 2;
                int c4  = (idx & 3) << 2;
                As[nxt][r][c4 + 0] = cvt_tf32(pa[it].x);
                As[nxt][r][c4 + 1] = cvt_tf32(pa[it].y);
                As[nxt][r][c4 + 2] = cvt_tf32(pa[it].z);
                As[nxt][r][c4 + 3] = cvt_tf32(pa[it].w);
            }
#pragma unroll
            for (int it = 0; it < 2; it++) {
                int idx = tid + it * 256;
                int kk  = idx >> 5;
                int n4  = (idx & 31) << 2;
                Bs[nxt][kk][n4 + 0] = cvt_tf32(pb[it].x);
                Bs[nxt][kk][n4 + 1] = cvt_tf32(pb[it].y);
                Bs[nxt][kk][n4 + 2] = cvt_tf32(pb[it].z);
                Bs[nxt][kk][n4 + 3] = cvt_tf32(pb[it].w);
            }
            __syncthreads();
            cur = nxt;
        }
    }

#pragma unroll
    for (int mf = 0; mf < 4; mf++) {
        int row0 = block_row + warp_m * 64 + mf * 16 + gId;
#pragma unroll
        for (int nf = 0; nf < 4; nf++) {
            int col = warp_n * 32 + nf * 8 + t4 * 2;
            if (row0 < NN)
                *(float2*)(d_Y + (size_t)row0 * 128 + col) =
                    make_float2(acc[mf][nf][0], acc[mf][nf][1]);
            if (row0 + 8 < NN)
                *(float2*)(d_Y + (size_t)(row0 + 8) * 128 + col) =
                    make_float2(acc[mf][nf][2], acc[mf][nf][3]);
        }
    }
}

// ---------------------------------------------------------------- layer-1 gather: h1 = relu(mean(y_l[nbr]) + y_r + b1)
// one warp per node; half-warp = one neighbor; 16 lanes x float4 = 64 feats
__global__ void __launch_bounds__(256) gather1_kernel(const float* __restrict__ b1) {
    int warp = (blockIdx.x * blockDim.x + threadIdx.x) >> 5;
    if (warp >= NN) return;
    int lane = threadIdx.x & 31;
    int q    = (lane & 15) << 2;
    int half = lane >> 4;

    int off = d_off[warp];
    int dg  = d_degi[warp];

    float4 acc = make_float4(0.f, 0.f, 0.f, 0.f);
    for (int i = half; i < dg; i += 2) {
        int s = d_csr_src[off + i];
        const float4 v = *(const float4*)(d_Y + (size_t)s * 128 + q);
        acc.x += v.x; acc.y += v.y; acc.z += v.z; acc.w += v.w;
    }
    acc.x += __shfl_xor_sync(~0u, acc.x, 16);
    acc.y += __shfl_xor_sync(~0u, acc.y, 16);
    acc.z += __shfl_xor_sync(~0u, acc.z, 16);
    acc.w += __shfl_xor_sync(~0u, acc.w, 16);

    if (half == 0) {
        float inv = 1.f / fmaxf((float)dg, 1.f);
        float4 yr = *(const float4*)(d_Y + (size_t)warp * 128 + 64 + q);
        float4 bb = *(const float4*)(b1 + q);
        float4 o;
        o.x = fmaxf(acc.x * inv + yr.x + bb.x, 0.f);
        o.y = fmaxf(acc.y * inv + yr.y + bb.y, 0.f);
        o.z = fmaxf(acc.z * inv + yr.z + bb.z, 0.f);
        o.w = fmaxf(acc.w * inv + yr.w + bb.w, 0.f);
        *(float4*)(d_h1 + (size_t)warp * H1D + q) = o;
    }
}

// ---------------------------------------------------------------- layer-2 gather: mean2 = mean(h1[nbr])
__global__ void __launch_bounds__(256) gather2_kernel() {
    int warp = (blockIdx.x * blockDim.x + threadIdx.x) >> 5;
    if (warp >= NN) return;
    int lane = threadIdx.x & 31;
    int q    = (lane & 15) << 2;
    int half = lane >> 4;

    int off = d_off[warp];
    int dg  = d_degi[warp];

    float4 acc = make_float4(0.f, 0.f, 0.f, 0.f);
    for (int i = half; i < dg; i += 2) {
        int s = d_csr_src[off + i];
        const float4 v = *(const float4*)(d_h1 + (size_t)s * H1D + q);
        acc.x += v.x; acc.y += v.y; acc.z += v.z; acc.w += v.w;
    }
    acc.x += __shfl_xor_sync(~0u, acc.x, 16);
    acc.y += __shfl_xor_sync(~0u, acc.y, 16);
    acc.z += __shfl_xor_sync(~0u, acc.z, 16);
    acc.w += __shfl_xor_sync(~0u, acc.w, 16);

    if (half == 0) {
        float inv = 1.f / fmaxf((float)dg, 1.f);
        float4 o = make_float4(acc.x * inv, acc.y * inv, acc.z * inv, acc.w * inv);
        *(float4*)(d_mean2 + (size_t)warp * H1D + q) = o;
    }
}

// ---------------------------------------------------------------- per-graph reduction (batch is sorted int32)
#define NPB 512
__global__ void reduce_kernel(const int* __restrict__ batch) {
    int f = threadIdx.x & 63;
    int lane = threadIdx.x >> 6;
    int start = blockIdx.x * NPB;
    int end = start + NPB;
    if (end > NN) end = NN;

    float s1 = 0.f, s2 = 0.f, c = 0.f;
    int cur = -1;
    for (int n = start + lane; n < end; n += 4) {
        int g = clampi(batch[n], 0, NG - 1);
        if (g != cur) {
            if (cur >= 0) {
                atomicAdd(&d_gs1[cur * H1D + f], s1);
                atomicAdd(&d_gs2[cur * H1D + f], s2);
                if (f == 0) atomicAdd(&d_gcnt[cur], c);
            }
            cur = g; s1 = 0.f; s2 = 0.f; c = 0.f;
        }
        s1 += d_mean2[(size_t)n * H1D + f];
        s2 += d_h1[(size_t)n * H1D + f];
        c += 1.0f;
    }
    if (cur >= 0) {
        atomicAdd(&d_gs1[cur * H1D + f], s1);
        atomicAdd(&d_gs2[cur * H1D + f], s2);
        if (f == 0) atomicAdd(&d_gcnt[cur], c);
    }
}

// ---------------------------------------------------------------- final
__global__ void final_kernel(const float* __restrict__ w2l,
                             const float* __restrict__ b2,
                             const float* __restrict__ w2r,
                             const float* __restrict__ wfc,
                             const float* __restrict__ bfc,
                             float* __restrict__ out) {
    __shared__ float pooled[NG][H2D];
    __shared__ float logits[NG][NC];
    int tid = threadIdx.x;

    for (int idx = tid; idx < NG * H2D; idx += 256) {
        int g = idx >> 7;
        int j = idx & 127;
        float s = 0.f;
        const float* gs1 = d_gs1 + g * H1D;
        const float* gs2 = d_gs2 + g * H1D;
#pragma unroll 8
        for (int f = 0; f < H1D; f++)
            s += gs1[f] * w2l[f * H2D + j] + gs2[f] * w2r[f * H2D + j];
        pooled[g][j] = s / fmaxf(d_gcnt[g], 1.0f) + b2[j];
    }
    __syncthreads();

    for (int idx = tid; idx < NG * NC; idx += 256) {
        int g = idx / NC;
        int c = idx % NC;
        float s = bfc[c];
#pragma unroll 8
        for (int j = 0; j < H2D; j++)
            s += pooled[g][j] * wfc[j * NC + c];
        logits[g][c] = s;
    }
    __syncthreads();

    for (int g = tid; g < NG; g += 256) {
        float mx = -1e30f;
        for (int c = 0; c < NC; c++) mx = fmaxf(mx, logits[g][c]);
        float se = 0.f;
        for (int c = 0; c < NC; c++) se += expf(logits[g][c] - mx);
        float lse = mx + logf(se);
        for (int c = 0; c < NC; c++) out[g * NC + c] = logits[g][c] - lse;
    }
}

// ---------------------------------------------------------------- launch
extern "C" void kernel_launch(void* const* d_in, const int* in_sizes, int n_in,
                              void* d_out, int out_size) {
    const float* x     = (const float*)d_in[0];
    const int*   ei    = (const int*)d_in[1];
    const int*   batch = (const int*)d_in[2];
    const float* w1l   = (const float*)d_in[3];
    const float* b1l   = (const float*)d_in[4];
    const float* w1r   = (const float*)d_in[5];
    const float* w2l   = (const float*)d_in[6];
    const float* b2l   = (const float*)d_in[7];
    const float* w2r   = (const float*)d_in[8];
    const float* wfc   = (const float*)d_in[9];
    const float* bfc   = (const float*)d_in[10];
    float*       out   = (float*)d_out;

    const int E = in_sizes[1] / 2;

    init_kernel<<<(NN + 255) / 256, 256>>>();
    deg_kernel<<<(E + 255) / 256, 256>>>(ei, E);
    scan_kernel<<<1, 1024>>>();
    fill_kernel<<<(E + 255) / 256, 256>>>(ei, E);
    tf32gemm_kernel<<<(NN + 127) / 128, 256>>>(x, w1l, w1r);
    gather1_kernel<<<(NN * 32 + 255) / 256, 256>>>(b1l);
    gather2_kernel<<<(NN * 32 + 255) / 256, 256>>>();
    reduce_kernel<<<(NN + NPB - 1) / NPB, 256>>>(batch);
    final_kernel<<<1, 256>>>(w2l, b2l, w2r, wfc, bfc, out);
}

// round 8
// speedup vs baseline: 1.6971x; 1.0217x over previous
#include <cuda_runtime.h>
#include <cstdint>

#define NN 50000
#define EMAX 800000
#define F_IN 512
#define H1D 64
#define H2D 128
#define NC 10
#define NG 64

// ---- scratch (static device globals; no allocation) ----
__device__ float d_Y[NN * 128];      // [N,128]: cols 0..63 = x@w1_l, 64..127 = x@w1_r
__device__ float d_h1[NN * H1D];
__device__ float d_mean2[NN * H1D];  // layer-2 neighbor means
__device__ int   d_degi[NN];
__device__ int   d_off[NN + 1];
__device__ int   d_fill[NN];
__device__ int   d_csr_src[EMAX];
__device__ float d_gs1[NG * H1D];
__device__ float d_gs2[NG * H1D];
__device__ float d_gcnt[NG];

__device__ __forceinline__ int clampi(int v, int lo, int hi) {
    return min(max(v, lo), hi);
}

__device__ __forceinline__ float cvt_tf32(float f) {
    uint32_t u;
    asm("cvt.rna.tf32.f32 %0, %1;" : "=r"(u) : "f"(f));
    return __uint_as_float(u);
}

__device__ __forceinline__ void mma_tf32(float& d0, float& d1, float& d2, float& d3,
                                         uint32_t a0, uint32_t a1, uint32_t a2, uint32_t a3,
                                         uint32_t b0, uint32_t b1) {
    asm volatile("mma.sync.aligned.m16n8k8.row.col.f32.tf32.tf32.f32 "
                 "{%0,%1,%2,%3}, {%4,%5,%6,%7}, {%8,%9}, {%0,%1,%2,%3};"
                 : "+f"(d0), "+f"(d1), "+f"(d2), "+f"(d3)
                 : "r"(a0), "r"(a1), "r"(a2), "r"(a3), "r"(b0), "r"(b1));
}

// ---------------------------------------------------------------- init
__global__ void init_kernel() {
    int i = blockIdx.x * blockDim.x + threadIdx.x;
    if (i < NN) { d_degi[i] = 0; d_fill[i] = 0; }
    if (i < NG * H1D) { d_gs1[i] = 0.f; d_gs2[i] = 0.f; }
    if (i < NG) d_gcnt[i] = 0.f;
}

// ---------------------------------------------------------------- degree histogram (2 edges/thread for ILP)
__global__ void deg_kernel(const int* __restrict__ ei, int E) {
    int t = blockIdx.x * blockDim.x + threadIdx.x;
    int e0 = t * 2;
    if (e0 < E)     atomicAdd(&d_degi[clampi(ei[E + e0], 0, NN - 1)], 1);
    if (e0 + 1 < E) atomicAdd(&d_degi[clampi(ei[E + e0 + 1], 0, NN - 1)], 1);
}

// ---------------------------------------------------------------- exclusive scan over d_degi (single block, 1024 threads)
__global__ void scan_kernel() {
    const int T = 1024;
    int tid = threadIdx.x;
    int per = (NN + T - 1) / T;
    int start = tid * per;
    int end = min(start + per, NN);

    int sum = 0;
    for (int i = start; i < end; i++) sum += d_degi[i];

    __shared__ int warp_sums[32];
    int lane = tid & 31, w = tid >> 5;
    int v = sum;
#pragma unroll
    for (int o = 1; o < 32; o <<= 1) {
        int n = __shfl_up_sync(~0u, v, o);
        if (lane >= o) v += n;
    }
    if (lane == 31) warp_sums[w] = v;
    __syncthreads();
    if (w == 0) {
        int s = warp_sums[lane];
#pragma unroll
        for (int o = 1; o < 32; o <<= 1) {
            int n = __shfl_up_sync(~0u, s, o);
            if (lane >= o) s += n;
        }
        warp_sums[lane] = s;
    }
    __syncthreads();

    int excl = v - sum + (w > 0 ? warp_sums[w - 1] : 0);
    int run = excl;
    for (int i = start; i < end; i++) { d_off[i] = run; run += d_degi[i]; }
    if (tid == T - 1) d_off[NN] = run;
}

// ---------------------------------------------------------------- CSR fill (2 edges/thread)
__global__ void fill_kernel(const int* __restrict__ ei, int E) {
    int t = blockIdx.x * blockDim.x + threadIdx.x;
#pragma unroll
    for (int j = 0; j < 2; j++) {
        int e = t * 2 + j;
        if (e < E) {
            int s = clampi(ei[e], 0, NN - 1);
            int d = clampi(ei[E + e], 0, NN - 1);
            int pos = d_off[d] + atomicAdd(&d_fill[d], 1);
            if (pos < EMAX) d_csr_src[pos] = s;
        }
    }
}

// ---------------------------------------------------------------- tf32 tensor-core GEMM: Y = x @ [w1_l | w1_r]
#define AS_STRIDE 20
#define BS_STRIDE 136
__global__ void __launch_bounds__(256) tf32gemm_kernel(
        const float* __restrict__ x,
        const float* __restrict__ w1l,
        const float* __restrict__ w1r) {
    __shared__ float As[2][128][AS_STRIDE];
    __shared__ float Bs[2][16][BS_STRIDE];

    const int block_row = blockIdx.x * 128;
    const int tid  = threadIdx.x;
    const int lane = tid & 31;
    const int wid  = tid >> 5;
    const int warp_m = wid >> 2;
    const int warp_n = wid & 3;
    const int gId  = lane >> 2;
    const int t4   = lane & 3;

    float acc[4][4][4];
#pragma unroll
    for (int mf = 0; mf < 4; mf++)
#pragma unroll
        for (int nf = 0; nf < 4; nf++)
#pragma unroll
            for (int r = 0; r < 4; r++) acc[mf][nf][r] = 0.f;

    float4 pa[2], pb[2];

#pragma unroll
    for (int it = 0; it < 2; it++) {
        int idx = tid + it * 256;
        int r   = idx >> 2;
        int c4  = (idx & 3) << 2;
        int gr  = block_row + r;
        float4 v = make_float4(0.f, 0.f, 0.f, 0.f);
        if (gr < NN) v = *(const float4*)(x + (size_t)gr * F_IN + c4);
        As[0][r][c4 + 0] = cvt_tf32(v.x);
        As[0][r][c4 + 1] = cvt_tf32(v.y);
        As[0][r][c4 + 2] = cvt_tf32(v.z);
        As[0][r][c4 + 3] = cvt_tf32(v.w);
    }
#pragma unroll
    for (int it = 0; it < 2; it++) {
        int idx = tid + it * 256;
        int kk  = idx >> 5;
        int n4  = (idx & 31) << 2;
        const float* wsrc = (n4 < 64)
            ? (w1l + (size_t)kk * H1D + n4)
            : (w1r + (size_t)kk * H1D + (n4 - 64));
        float4 v = *(const float4*)wsrc;
        Bs[0][kk][n4 + 0] = cvt_tf32(v.x);
        Bs[0][kk][n4 + 1] = cvt_tf32(v.y);
        Bs[0][kk][n4 + 2] = cvt_tf32(v.z);
        Bs[0][kk][n4 + 3] = cvt_tf32(v.w);
    }
    __syncthreads();

    int cur = 0;
    for (int kt = 0; kt < F_IN / 16; kt++) {
        const int knext = (kt + 1) * 16;
        const bool has_next = (knext < F_IN);

        if (has_next) {
#pragma unroll
            for (int it = 0; it < 2; it++) {
                int idx = tid + it * 256;
                int r   = idx >> 2;
                int c4  = (idx & 3) << 2;
                int gr  = block_row + r;
                pa[it] = make_float4(0.f, 0.f, 0.f, 0.f);
                if (gr < NN)
                    pa[it] = *(const float4*)(x + (size_t)gr * F_IN + knext + c4);
            }
#pragma unroll
            for (int it = 0; it < 2; it++) {
                int idx = tid + it * 256;
                int kk  = idx >> 5;
                int n4  = (idx & 31) << 2;
                const float* wsrc = (n4 < 64)
                    ? (w1l + (size_t)(knext + kk) * H1D + n4)
                    : (w1r + (size_t)(knext + kk) * H1D + (n4 - 64));
                pb[it] = *(const float4*)wsrc;
            }
        }

#pragma unroll
        for (int k8 = 0; k8 < 2; k8++) {
            const int kc = k8 * 8 + t4;
            uint32_t a[4][4], b[4][2];
#pragma unroll
            for (int mf = 0; mf < 4; mf++) {
                int row = warp_m * 64 + mf * 16 + gId;
                a[mf][0] = __float_as_uint(As[cur][row][kc]);
                a[mf][1] = __float_as_uint(As[cur][row + 8][kc]);
                a[mf][2] = __float_as_uint(As[cur][row][kc + 4]);
                a[mf][3] = __float_as_uint(As[cur][row + 8][kc + 4]);
            }
#pragma unroll
            for (int nf = 0; nf < 4; nf++) {
                int col = warp_n * 32 + nf * 8 + gId;
                b[nf][0] = __float_as_uint(Bs[cur][k8 * 8 + t4][col]);
                b[nf][1] = __float_as_uint(Bs[cur][k8 * 8 + t4 + 4][col]);
            }
#pragma unroll
            for (int mf = 0; mf < 4; mf++)
#pragma unroll
                for (int nf = 0; nf < 4; nf++)
                    mma_tf32(acc[mf][nf][0], acc[mf][nf][1], acc[mf][nf][2], acc[mf][nf][3],
                             a[mf][0], a[mf][1], a[mf][2], a[mf][3],
                             b[nf][0], b[nf][1]);
        }

        if (has_next) {
            int nxt = cur ^ 1;
#pragma unroll
            for (int it = 0; it < 2; it++) {
                int idx = tid + it * 256;
                int r   = idx >> 2;
                int c4  = (idx & 3) << 2;
                As[nxt][r][c4 + 0] = cvt_tf32(pa[it].x);
                As[nxt][r][c4 + 1] = cvt_tf32(pa[it].y);
                As[nxt][r][c4 + 2] = cvt_tf32(pa[it].z);
                As[nxt][r][c4 + 3] = cvt_tf32(pa[it].w);
            }
#pragma unroll
            for (int it = 0; it < 2; it++) {
                int idx = tid + it * 256;
                int kk  = idx >> 5;
                int n4  = (idx & 31) << 2;
                Bs[nxt][kk][n4 + 0] = cvt_tf32(pb[it].x);
                Bs[nxt][kk][n4 + 1] = cvt_tf32(pb[it].y);
                Bs[nxt][kk][n4 + 2] = cvt_tf32(pb[it].z);
                Bs[nxt][kk][n4 + 3] = cvt_tf32(pb[it].w);
            }
            __syncthreads();
            cur = nxt;
        }
    }

#pragma unroll
    for (int mf = 0; mf < 4; mf++) {
        int row0 = block_row + warp_m * 64 + mf * 16 + gId;
#pragma unroll
        for (int nf = 0; nf < 4; nf++) {
            int col = warp_n * 32 + nf * 8 + t4 * 2;
            if (row0 < NN)
                *(float2*)(d_Y + (size_t)row0 * 128 + col) =
                    make_float2(acc[mf][nf][0], acc[mf][nf][1]);
            if (row0 + 8 < NN)
                *(float2*)(d_Y + (size_t)(row0 + 8) * 128 + col) =
                    make_float2(acc[mf][nf][2], acc[mf][nf][3]);
        }
    }
}

// ---------------------------------------------------------------- gathers: one warp per node, lane owns a float2 feature pair.
// Neighbor loop unrolled x8 -> 8 independent (index, row) load pairs in flight.
#define GUNROLL 8
__global__ void __launch_bounds__(256) gather1_kernel(const float* __restrict__ b1) {
    int node = (blockIdx.x * blockDim.x + threadIdx.x) >> 5;
    if (node >= NN) return;
    int lane = threadIdx.x & 31;
    int f2 = lane * 2;

    int off = d_off[node];
    int dg  = d_degi[node];

    float sx = 0.f, sy = 0.f;
    int i = 0;
    for (; i + GUNROLL <= dg; i += GUNROLL) {
        int s[GUNROLL];
#pragma unroll
        for (int j = 0; j < GUNROLL; j++) s[j] = __ldg(&d_csr_src[off + i + j]);
        float2 v[GUNROLL];
#pragma unroll
        for (int j = 0; j < GUNROLL; j++)
            v[j] = *(const float2*)(d_Y + (size_t)s[j] * 128 + f2);
#pragma unroll
        for (int j = 0; j < GUNROLL; j++) { sx += v[j].x; sy += v[j].y; }
    }
    for (; i < dg; i++) {
        int s = __ldg(&d_csr_src[off + i]);
        float2 v = *(const float2*)(d_Y + (size_t)s * 128 + f2);
        sx += v.x; sy += v.y;
    }

    float inv = 1.f / fmaxf((float)dg, 1.f);
    float2 yr = *(const float2*)(d_Y + (size_t)node * 128 + 64 + f2);
    float2 bb = *(const float2*)(b1 + f2);
    float2 o;
    o.x = fmaxf(sx * inv + yr.x + bb.x, 0.f);
    o.y = fmaxf(sy * inv + yr.y + bb.y, 0.f);
    *(float2*)(d_h1 + (size_t)node * H1D + f2) = o;
}

__global__ void __launch_bounds__(256) gather2_kernel() {
    int node = (blockIdx.x * blockDim.x + threadIdx.x) >> 5;
    if (node >= NN) return;
    int lane = threadIdx.x & 31;
    int f2 = lane * 2;

    int off = d_off[node];
    int dg  = d_degi[node];

    float sx = 0.f, sy = 0.f;
    int i = 0;
    for (; i + GUNROLL <= dg; i += GUNROLL) {
        int s[GUNROLL];
#pragma unroll
        for (int j = 0; j < GUNROLL; j++) s[j] = __ldg(&d_csr_src[off + i + j]);
        float2 v[GUNROLL];
#pragma unroll
        for (int j = 0; j < GUNROLL; j++)
            v[j] = *(const float2*)(d_h1 + (size_t)s[j] * H1D + f2);
#pragma unroll
        for (int j = 0; j < GUNROLL; j++) { sx += v[j].x; sy += v[j].y; }
    }
    for (; i < dg; i++) {
        int s = __ldg(&d_csr_src[off + i]);
        float2 v = *(const float2*)(d_h1 + (size_t)s * H1D + f2);
        sx += v.x; sy += v.y;
    }

    float inv = 1.f / fmaxf((float)dg, 1.f);
    *(float2*)(d_mean2 + (size_t)node * H1D + f2) = make_float2(sx * inv, sy * inv);
}

// ---------------------------------------------------------------- per-graph reduction (batch is sorted int32)
#define NPB 512
__global__ void reduce_kernel(const int* __restrict__ batch) {
    int f = threadIdx.x & 63;
    int lane = threadIdx.x >> 6;
    int start = blockIdx.x * NPB;
    int end = start + NPB;
    if (end > NN) end = NN;

    float s1 = 0.f, s2 = 0.f, c = 0.f;
    int cur = -1;
    for (int n = start + lane; n < end; n += 4) {
        int g = clampi(batch[n], 0, NG - 1);
        if (g != cur) {
            if (cur >= 0) {
                atomicAdd(&d_gs1[cur * H1D + f], s1);
                atomicAdd(&d_gs2[cur * H1D + f], s2);
                if (f == 0) atomicAdd(&d_gcnt[cur], c);
            }
            cur = g; s1 = 0.f; s2 = 0.f; c = 0.f;
        }
        s1 += d_mean2[(size_t)n * H1D + f];
        s2 += d_h1[(size_t)n * H1D + f];
        c += 1.0f;
    }
    if (cur >= 0) {
        atomicAdd(&d_gs1[cur * H1D + f], s1);
        atomicAdd(&d_gs2[cur * H1D + f], s2);
        if (f == 0) atomicAdd(&d_gcnt[cur], c);
    }
}

// ---------------------------------------------------------------- final
__global__ void final_kernel(const float* __restrict__ w2l,
                             const float* __restrict__ b2,
                             const float* __restrict__ w2r,
                             const float* __restrict__ wfc,
                             const float* __restrict__ bfc,
                             float* __restrict__ out) {
    __shared__ float pooled[NG][H2D];
    __shared__ float logits[NG][NC];
    int tid = threadIdx.x;

    for (int idx = tid; idx < NG * H2D; idx += 256) {
        int g = idx >> 7;
        int j = idx & 127;
        float s = 0.f;
        const float* gs1 = d_gs1 + g * H1D;
        const float* gs2 = d_gs2 + g * H1D;
#pragma unroll 8
        for (int f = 0; f < H1D; f++)
            s += gs1[f] * w2l[f * H2D + j] + gs2[f] * w2r[f * H2D + j];
        pooled[g][j] = s / fmaxf(d_gcnt[g], 1.0f) + b2[j];
    }
    __syncthreads();

    for (int idx = tid; idx < NG * NC; idx += 256) {
        int g = idx / NC;
        int c = idx % NC;
        float s = bfc[c];
#pragma unroll 8
        for (int j = 0; j < H2D; j++)
            s += pooled[g][j] * wfc[j * NC + c];
        logits[g][c] = s;
    }
    __syncthreads();

    for (int g = tid; g < NG; g += 256) {
        float mx = -1e30f;
        for (int c = 0; c < NC; c++) mx = fmaxf(mx, logits[g][c]);
        float se = 0.f;
        for (int c = 0; c < NC; c++) se += expf(logits[g][c] - mx);
        float lse = mx + logf(se);
        for (int c = 0; c < NC; c++) out[g * NC + c] = logits[g][c] - lse;
    }
}

// ---------------------------------------------------------------- launch
extern "C" void kernel_launch(void* const* d_in, const int* in_sizes, int n_in,
                              void* d_out, int out_size) {
    const float* x     = (const float*)d_in[0];
    const int*   ei    = (const int*)d_in[1];
    const int*   batch = (const int*)d_in[2];
    const float* w1l   = (const float*)d_in[3];
    const float* b1l   = (const float*)d_in[4];
    const float* w1r   = (const float*)d_in[5];
    const float* w2l   = (const float*)d_in[6];
    const float* b2l   = (const float*)d_in[7];
    const float* w2r   = (const float*)d_in[8];
    const float* wfc   = (const float*)d_in[9];
    const float* bfc   = (const float*)d_in[10];
    float*       out   = (float*)d_out;

    const int E = in_sizes[1] / 2;

    init_kernel<<<(NN + 255) / 256, 256>>>();
    deg_kernel<<<(E / 2 + 255) / 256, 256>>>(ei, E);
    scan_kernel<<<1, 1024>>>();
    fill_kernel<<<(E / 2 + 255) / 256, 256>>>(ei, E);
    tf32gemm_kernel<<<(NN + 127) / 128, 256>>>(x, w1l, w1r);
    gather1_kernel<<<(NN * 32 + 255) / 256, 256>>>(b1l);
    gather2_kernel<<<(NN * 32 + 255) / 256, 256>>>();
    reduce_kernel<<<(NN + NPB - 1) / NPB, 256>>>(batch);
    final_kernel<<<1, 256>>>(w2l, b2l, w2r, wfc, bfc, out);
}